// round 6
// baseline (speedup 1.0000x reference)
#include <cuda_runtime.h>
#include <cuda_bf16.h>
#include <math.h>

#define B    4
#define C    256
#define CQK  16
#define N    4096
#define MT   128
#define NT   64
#define NTILES (N / NT)
#define LOG2E 1.4426950408889634f

#define KD   24      // q/k tile row stride (bf16): 48B, conflict-free ldsm
#define VB   72      // v tile row stride (bf16): 144B
#define PB   136     // p tile row stride (bf16): 272B

typedef unsigned long long u64;
typedef unsigned int u32;

// Scratch: q,k bf16 [B][N][16] (q pre-scaled by log2e); v bf16 [B][C][N]
__device__ __nv_bfloat16 g_q[(size_t)B * N * CQK];
__device__ __nv_bfloat16 g_k[(size_t)B * N * CQK];
__device__ __nv_bfloat16 g_v[(size_t)B * C * N];

// ---- f32x2 helpers ----------------------------------------------------------
__device__ __forceinline__ u64 pk2(float lo, float hi) {
    u64 r; asm("mov.b64 %0,{%1,%2};" : "=l"(r) : "f"(lo), "f"(hi)); return r;
}
__device__ __forceinline__ u64 fma2(u64 a, u64 b, u64 c) {
    u64 d; asm("fma.rn.f32x2 %0,%1,%2,%3;" : "=l"(d) : "l"(a), "l"(b), "l"(c)); return d;
}
__device__ __forceinline__ float2 up2(u64 a) {
    float2 f; asm("mov.b64 {%0,%1},%2;" : "=f"(f.x), "=f"(f.y) : "l"(a)); return f;
}

// ---- tensor-core / bf16 helpers ----------------------------------------------
__device__ __forceinline__ void ldsm4(u32* r, const void* p) {
    u32 a = (u32)__cvta_generic_to_shared(p);
    asm volatile("ldmatrix.sync.aligned.m8n8.x4.shared.b16 {%0,%1,%2,%3},[%4];"
                 : "=r"(r[0]), "=r"(r[1]), "=r"(r[2]), "=r"(r[3]) : "r"(a));
}
__device__ __forceinline__ void ldsm4t(u32* r, const void* p) {
    u32 a = (u32)__cvta_generic_to_shared(p);
    asm volatile("ldmatrix.sync.aligned.m8n8.x4.trans.shared.b16 {%0,%1,%2,%3},[%4];"
                 : "=r"(r[0]), "=r"(r[1]), "=r"(r[2]), "=r"(r[3]) : "r"(a));
}
__device__ __forceinline__ void mma_bf16(float* d, const u32* a, const u32* b) {
    asm volatile("mma.sync.aligned.m16n8k16.row.col.f32.bf16.bf16.f32 "
                 "{%0,%1,%2,%3},{%4,%5,%6,%7},{%8,%9},{%0,%1,%2,%3};"
                 : "+f"(d[0]), "+f"(d[1]), "+f"(d[2]), "+f"(d[3])
                 : "r"(a[0]), "r"(a[1]), "r"(a[2]), "r"(a[3]), "r"(b[0]), "r"(b[1]));
}
__device__ __forceinline__ u32 bf2(float lo, float hi) {
    u32 r; asm("cvt.rn.bf16x2.f32 %0,%1,%2;" : "=r"(r) : "f"(hi), "f"(lo)); return r;
}
__device__ __forceinline__ u32 ex2b2(u32 s) {
    u32 d; asm("ex2.approx.ftz.bf16x2 %0,%1;" : "=r"(d) : "r"(s)); return d;
}
__device__ __forceinline__ u32 addb2(u32 a, u32 b) {
    u32 d; asm("add.rn.bf16x2 %0,%1,%2;" : "=r"(d) : "r"(a), "r"(b)); return d;
}

// ---------------------------------------------------------------------------
// Projection. grid (N/512, B, 9). 2 pixels/thread.
// z<8: v chunk (32 ch) -> g_v bf16 [c][n]; z==8: q (x log2e) + k -> [n][16] bf16.
// ---------------------------------------------------------------------------
__global__ __launch_bounds__(256) void proj_kernel(
    const float* __restrict__ x,
    const float* __restrict__ Wq, const float* __restrict__ bq,
    const float* __restrict__ Wk, const float* __restrict__ bk,
    const float* __restrict__ Wv, const float* __restrict__ bv)
{
    __shared__ float w_t[C * 32];   // [c][o]
    const int t = threadIdx.x;
    const int b = blockIdx.y;
    const int z = blockIdx.z;

    if (z < 8) {
        for (int idx = t; idx < C * 32; idx += 256) {
            int c = idx >> 5, o = idx & 31;
            w_t[idx] = Wv[(size_t)(z * 32 + o) * C + c];
        }
    } else {
        for (int idx = t; idx < C * 32; idx += 256) {
            int c = idx >> 5, o = idx & 31;
            w_t[idx] = (o < 16) ? Wq[(size_t)o * C + c] * LOG2E
                                : Wk[(size_t)(o - 16) * C + c];
        }
    }
    __syncthreads();

    const int n = blockIdx.x * 512 + t;   // pixels n, n+256
    const float* xb = x + (size_t)b * C * N + n;

    u64 a0[16], a1[16];
    if (z < 8) {
        #pragma unroll
        for (int j = 0; j < 16; j++) {
            a0[j] = pk2(bv[z * 32 + 2 * j], bv[z * 32 + 2 * j + 1]);
            a1[j] = a0[j];
        }
    } else {
        #pragma unroll
        for (int j = 0; j < 16; j++) {
            a0[j] = (j < 8) ? pk2(bq[2 * j] * LOG2E, bq[2 * j + 1] * LOG2E)
                            : pk2(bk[2 * (j - 8)], bk[2 * (j - 8) + 1]);
            a1[j] = a0[j];
        }
    }

    #pragma unroll 4
    for (int c = 0; c < C; c++) {
        float xv0 = xb[(size_t)c * N];
        float xv1 = xb[(size_t)c * N + 256];
        u64 xx0 = pk2(xv0, xv0);
        u64 xx1 = pk2(xv1, xv1);
        const u64* wr = (const u64*)&w_t[c * 32];
        #pragma unroll
        for (int j = 0; j < 16; j++) {
            u64 w = wr[j];
            a0[j] = fma2(xx0, w, a0[j]);
            a1[j] = fma2(xx1, w, a1[j]);
        }
    }

    if (z < 8) {
        #pragma unroll
        for (int j = 0; j < 16; j++) {
            float2 f0 = up2(a0[j]);
            float2 f1 = up2(a1[j]);
            size_t r0 = ((size_t)b * C + z * 32 + 2 * j) * N + n;
            g_v[r0]           = __float2bfloat16_rn(f0.x);
            g_v[r0 + N]       = __float2bfloat16_rn(f0.y);
            g_v[r0 + 256]     = __float2bfloat16_rn(f1.x);
            g_v[r0 + N + 256] = __float2bfloat16_rn(f1.y);
        }
    } else {
        u32 w0[8], w1[8];
        #pragma unroll
        for (int j = 0; j < 8; j++) {
            float2 q0 = up2(a0[j]), q1 = up2(a1[j]);
            float2 k0 = up2(a0[j + 8]), k1 = up2(a1[j + 8]);
            w0[j] = bf2(q0.x, q0.y);
            w1[j] = bf2(q1.x, q1.y);
            a0[j] = ((u64)bf2(k0.x, k0.y)) | ((u64)bf2(k1.x, k1.y) << 32);
        }
        uint4* qd0 = (uint4*)&g_q[((size_t)b * N + n) * CQK];
        uint4* qd1 = (uint4*)&g_q[((size_t)b * N + n + 256) * CQK];
        qd0[0] = make_uint4(w0[0], w0[1], w0[2], w0[3]);
        qd0[1] = make_uint4(w0[4], w0[5], w0[6], w0[7]);
        qd1[0] = make_uint4(w1[0], w1[1], w1[2], w1[3]);
        qd1[1] = make_uint4(w1[4], w1[5], w1[6], w1[7]);
        uint4* kd0 = (uint4*)&g_k[((size_t)b * N + n) * CQK];
        uint4* kd1 = (uint4*)&g_k[((size_t)b * N + n + 256) * CQK];
        kd0[0] = make_uint4((u32)a0[0], (u32)a0[1], (u32)a0[2], (u32)a0[3]);
        kd0[1] = make_uint4((u32)a0[4], (u32)a0[5], (u32)a0[6], (u32)a0[7]);
        kd1[0] = make_uint4((u32)(a0[0] >> 32), (u32)(a0[1] >> 32), (u32)(a0[2] >> 32), (u32)(a0[3] >> 32));
        kd1[1] = make_uint4((u32)(a0[4] >> 32), (u32)(a0[5] >> 32), (u32)(a0[6] >> 32), (u32)(a0[7] >> 32));
    }
}

// ---------------------------------------------------------------------------
// Flash attention, full-HMMA, S(t+1) overlapped with PV(t).
// Block (m-tile 128, b), 512 threads (16 warps).
// ---------------------------------------------------------------------------
// smem float offsets
#define OFF_K 0                              // [128][KD] bf16
#define OFF_Q (OFF_K + (MT*KD)/2)            // 3 x [64][KD] bf16
#define OFF_L (OFF_Q + (3*NT*KD)/2)          // [128] f32
#define OFF_P (OFF_L + MT)                   // 2 x [64][PB] bf16
#define OFF_V (OFF_P + (2*NT*PB)/2)          // 3 x [256][VB] bf16
#define ATT_SMEM_FLOATS (OFF_V + (3*C*VB)/2)

__global__ __launch_bounds__(512, 1) void attn_kernel(
    const float* __restrict__ x,
    const float* __restrict__ gamma,
    float* __restrict__ out)
{
    extern __shared__ float sm[];
    __nv_bfloat16* k_s  = (__nv_bfloat16*)(sm + OFF_K);
    __nv_bfloat16* q_s  = (__nv_bfloat16*)(sm + OFF_Q);
    float*         L_s  = sm + OFF_L;
    __nv_bfloat16* p_bf = (__nv_bfloat16*)(sm + OFF_P);
    __nv_bfloat16* v_bf = (__nv_bfloat16*)(sm + OFF_V);

    const int t    = threadIdx.x;
    const int b    = blockIdx.y;
    const int m0   = blockIdx.x * MT;
    const int lane = t & 31;
    const int w    = t >> 5;

    // warp roles
    const int ng  = w & 3;            // S: n-group (16 rows)
    const int mg2 = w >> 2;           // S: m-group (32 cols)
    const int ct0 = (w & 7) * 32;     // PV: 32 channels
    const int mw  = (w >> 3) * 64;    // PV: 64 m-cols

    // ldmatrix lane mappings
    const int mi = lane >> 3;
    const int lr = ((mi & 1) << 3) + (lane & 7);       // A rows
    const int lc = (mi >> 1) << 3;                     // A col offset
    const int br = (lane & 7) + ((lane >> 4) << 3);    // B rows
    const int bc = ((lane >> 3) & 1) << 3;             // B col offset

    const int r  = lane >> 2;
    const int cq = (lane & 3) * 2;

    // init: K tile, L_s
    if (t < 256) {
        int m = t >> 1, half = t & 1;
        *(uint4*)(k_s + m * KD + half * 8) =
            *(const uint4*)(g_k + ((size_t)b * N + m0 + m) * CQK + half * 8);
    }
    if (t < MT) L_s[t] = 0.f;

    auto load_tile = [&](int tile) {
        const int n0  = tile * NT;
        const int buf = tile % 3;
        if (t < 128) {
            int n = t >> 1, half = t & 1;
            *(uint4*)(q_s + buf * NT * KD + n * KD + half * 8) =
                *(const uint4*)(g_q + ((size_t)b * N + n0 + n) * CQK + half * 8);
        }
        __nv_bfloat16* vd = v_bf + buf * C * VB;
        #pragma unroll
        for (int rr = 0; rr < 4; rr++) {
            int idx = t + rr * 512;
            int c = idx >> 3, q8 = idx & 7;
            *(uint4*)(vd + c * VB + q8 * 8) =
                *(const uint4*)(g_v + ((size_t)b * C + c) * N + n0 + q8 * 8);
        }
    };

    load_tile(0);
    load_tile(1);
    __syncthreads();

    // ---- hoist K fragments (constant for whole block) ----
    u32 kb0[4], kb1[4];
    ldsm4(kb0, k_s + (mg2 * 32      + br) * KD + bc);
    ldsm4(kb1, k_s + (mg2 * 32 + 16 + br) * KD + bc);

    // ---- S-phase lambda: scores + exp + L partials for `tile` ----
    auto s_compute = [&](int tile) {
        const __nv_bfloat16* qb = q_s + (tile % 3) * NT * KD;
        u32 a[4];
        ldsm4(a, qb + (ng * 16 + lr) * KD + lc);
        float ds[4][4];
        #pragma unroll
        for (int j = 0; j < 4; j++)
            #pragma unroll
            for (int e = 0; e < 4; e++) ds[j][e] = 0.f;
        mma_bf16(ds[0], a, kb0);
        mma_bf16(ds[1], a, kb0 + 2);
        mma_bf16(ds[2], a, kb1);
        mma_bf16(ds[3], a, kb1 + 2);

        __nv_bfloat16* pb = p_bf + (tile & 1) * NT * PB;
        #pragma unroll
        for (int j = 0; j < 4; j++) {
            int cj = mg2 * 32 + j * 8 + cq;
            u32 e0 = ex2b2(bf2(ds[j][0], ds[j][1]));   // row ng*16+r
            u32 e1 = ex2b2(bf2(ds[j][2], ds[j][3]));   // row ng*16+r+8
            *(u32*)(pb + (ng * 16 + r)     * PB + cj) = e0;
            *(u32*)(pb + (ng * 16 + r + 8) * PB + cj) = e1;
            u32 s2 = addb2(e0, e1);
            s2 = addb2(s2, __shfl_xor_sync(0xffffffffu, s2, 4));
            s2 = addb2(s2, __shfl_xor_sync(0xffffffffu, s2, 8));
            s2 = addb2(s2, __shfl_xor_sync(0xffffffffu, s2, 16));
            if (lane < 4) {
                atomicAdd(&L_s[cj],     __uint_as_float(s2 << 16));
                atomicAdd(&L_s[cj + 1], __uint_as_float(s2 & 0xffff0000u));
            }
        }
    };

    float d_acc[2][8][4];
    #pragma unroll
    for (int ct = 0; ct < 2; ct++)
        #pragma unroll
        for (int mt = 0; mt < 8; mt++)
            #pragma unroll
            for (int j = 0; j < 4; j++) d_acc[ct][mt][j] = 0.f;

    s_compute(0);
    __syncthreads();   // p[0] ready

    for (int tile = 0; tile < NTILES; ++tile) {
        // prefetch tile+2 (buffer (tile+2)%3 = (tile-1)%3, free after prev barrier)
        if (tile + 2 < NTILES) load_tile(tile + 2);

        // S for the NEXT tile (writes p[(tile+1)&1]) — overlaps with PV below
        if (tile + 1 < NTILES) s_compute(tile + 1);

        // ---- PV: O += V(tile) P(tile) ----
        {
            const __nv_bfloat16* vc = v_bf + (tile % 3) * C * VB;
            const __nv_bfloat16* pc = p_bf + (tile & 1) * NT * PB;
            #pragma unroll
            for (int ks = 0; ks < 4; ks++) {
                u32 av[2][4];
                ldsm4(av[0], vc + (ct0      + lr) * VB + ks * 16 + lc);
                ldsm4(av[1], vc + (ct0 + 16 + lr) * VB + ks * 16 + lc);
                #pragma unroll
                for (int mtp = 0; mtp < 4; mtp++) {
                    u32 bfr[4];
                    ldsm4t(bfr, pc + (ks * 16 + lr) * PB + mw + mtp * 16 + lc);
                    mma_bf16(d_acc[0][2 * mtp    ], av[0], bfr    );
                    mma_bf16(d_acc[0][2 * mtp + 1], av[0], bfr + 2);
                    mma_bf16(d_acc[1][2 * mtp    ], av[1], bfr    );
                    mma_bf16(d_acc[1][2 * mtp + 1], av[1], bfr + 2);
                }
            }
        }
        __syncthreads();
    }

    if (t < MT) L_s[t] = 1.0f / L_s[t];
    __syncthreads();

    // ---- epilogue: out = x + gamma * O / L ----
    const float g  = gamma[0];
    const int  rr = lane >> 2;
    const int  ql = lane & 3;
    #pragma unroll
    for (int ct = 0; ct < 2; ct++) {
        #pragma unroll
        for (int half = 0; half < 2; half++) {
            int c = ct0 + ct * 16 + rr + half * 8;
            #pragma unroll
            for (int mt = 0; mt < 8; mt++) {
                int mloc = mw + mt * 8 + ql * 2;
                float iL0 = L_s[mloc], iL1 = L_s[mloc + 1];
                size_t idx = ((size_t)b * C + c) * N + m0 + mloc;
                float2 xv = *(const float2*)&x[idx];
                float2 ov;
                ov.x = xv.x + g * d_acc[ct][mt][half * 2    ] * iL0;
                ov.y = xv.y + g * d_acc[ct][mt][half * 2 + 1] * iL1;
                *(float2*)&out[idx] = ov;
            }
        }
    }
}

// ---------------------------------------------------------------------------
extern "C" void kernel_launch(void* const* d_in, const int* in_sizes, int n_in,
                              void* d_out, int out_size)
{
    const float* x     = (const float*)d_in[0];
    const float* Wq    = (const float*)d_in[1];
    const float* bq    = (const float*)d_in[2];
    const float* Wk    = (const float*)d_in[3];
    const float* bk    = (const float*)d_in[4];
    const float* Wv    = (const float*)d_in[5];
    const float* bv    = (const float*)d_in[6];
    const float* gamma = (const float*)d_in[7];
    float* out = (float*)d_out;

    proj_kernel<<<dim3(N / 512, B, 9), 256>>>(x, Wq, bq, Wk, bk, Wv, bv);

    const int smem_bytes = ATT_SMEM_FLOATS * (int)sizeof(float);
    cudaFuncSetAttribute(attn_kernel,
                         cudaFuncAttributeMaxDynamicSharedMemorySize, smem_bytes);
    attn_kernel<<<dim3(N / MT, B), 512, smem_bytes>>>(x, gamma, out);
}

// round 9
// speedup vs baseline: 1.1175x; 1.1175x over previous
#include <cuda_runtime.h>
#include <cuda_bf16.h>

#define B    4
#define C    256
#define CQK  16
#define N    4096
#define MT   128
#define NT   64
#define NTILES (N / NT)
#define LOG2E 1.4426950408889634f
#define SBIAS 20.0f     // P = 2^(s*log2e - SBIAS); cancels in o/L

typedef unsigned long long u64;
typedef unsigned int u32;
typedef unsigned short u16;
typedef unsigned char u8;

// Scratch: q,k bf16 [B][N][16] (q pre-scaled by log2e); v e4m3 [B][C][N]
__device__ __nv_bfloat16 g_q[(size_t)B * N * CQK];
__device__ __nv_bfloat16 g_k[(size_t)B * N * CQK];
__device__ u8            g_v[(size_t)B * C * N];

// ---- f32x2 helpers (projection) ---------------------------------------------
__device__ __forceinline__ u64 pk2(float lo, float hi) {
    u64 r; asm("mov.b64 %0,{%1,%2};" : "=l"(r) : "f"(lo), "f"(hi)); return r;
}
__device__ __forceinline__ u64 fma2(u64 a, u64 b, u64 c) {
    u64 d; asm("fma.rn.f32x2 %0,%1,%2,%3;" : "=l"(d) : "l"(a), "l"(b), "l"(c)); return d;
}
__device__ __forceinline__ float2 up2(u64 a) {
    float2 f; asm("mov.b64 {%0,%1},%2;" : "=f"(f.x), "=f"(f.y) : "l"(a)); return f;
}

// ---- bf16 / f16 / fp8 helpers --------------------------------------------------
__device__ __forceinline__ u32 bf2(float lo, float hi) {
    u32 r; asm("cvt.rn.bf16x2.f32 %0,%1,%2;" : "=r"(r) : "f"(hi), "f"(lo)); return r;
}
__device__ __forceinline__ u32 hpack(float lo, float hi) {
    u32 r; asm("cvt.rn.f16x2.f32 %0,%1,%2;" : "=r"(r) : "f"(hi), "f"(lo)); return r;
}
__device__ __forceinline__ u32 ex2h2(u32 s) {
    u32 d; asm("ex2.approx.f16x2 %0,%1;" : "=r"(d) : "r"(s)); return d;
}
__device__ __forceinline__ u32 hadd2(u32 a, u32 b) {
    u32 d; asm("add.rn.f16x2 %0,%1,%2;" : "=r"(d) : "r"(a), "r"(b)); return d;
}
__device__ __forceinline__ u16 e4m3h2(u32 h) {
    u16 d; asm("cvt.rn.satfinite.e4m3x2.f16x2 %0,%1;" : "=h"(d) : "r"(h)); return d;
}
__device__ __forceinline__ u16 e4m3f2(float lo, float hi) {
    u16 d; asm("cvt.rn.satfinite.e4m3x2.f32 %0,%1,%2;" : "=h"(d) : "f"(hi), "f"(lo)); return d;
}
__device__ __forceinline__ float h2sum(u32 h) {
    float a, b;
    asm("{.reg .f16 x,y; mov.b32 {x,y},%2; cvt.f32.f16 %0,x; cvt.f32.f16 %1,y;}"
        : "=f"(a), "=f"(b) : "r"(h));
    return a + b;
}

// ---- tensor-core helpers --------------------------------------------------------
__device__ __forceinline__ void ldsm4(u32* r, const void* p) {
    u32 a = (u32)__cvta_generic_to_shared(p);
    asm volatile("ldmatrix.sync.aligned.m8n8.x4.shared.b16 {%0,%1,%2,%3},[%4];"
                 : "=r"(r[0]), "=r"(r[1]), "=r"(r[2]), "=r"(r[3]) : "r"(a));
}
__device__ __forceinline__ void mma_bf16(float* d, const u32* a, const u32* b) {
    asm volatile("mma.sync.aligned.m16n8k16.row.col.f32.bf16.bf16.f32 "
                 "{%0,%1,%2,%3},{%4,%5,%6,%7},{%8,%9},{%0,%1,%2,%3};"
                 : "+f"(d[0]), "+f"(d[1]), "+f"(d[2]), "+f"(d[3])
                 : "r"(a[0]), "r"(a[1]), "r"(a[2]), "r"(a[3]), "r"(b[0]), "r"(b[1]));
}
__device__ __forceinline__ void mma_e4m3(float* d, const u32* a, const u32* b) {
    asm volatile("mma.sync.aligned.m16n8k32.row.col.f32.e4m3.e4m3.f32 "
                 "{%0,%1,%2,%3},{%4,%5,%6,%7},{%8,%9},{%0,%1,%2,%3};"
                 : "+f"(d[0]), "+f"(d[1]), "+f"(d[2]), "+f"(d[3])
                 : "r"(a[0]), "r"(a[1]), "r"(a[2]), "r"(a[3]), "r"(b[0]), "r"(b[1]));
}

// ---------------------------------------------------------------------------
// Projection. grid (N/512, B, 9), 256 thr, 2 consecutive pixels/thread.
// z<8: v chunk (32 ch) -> g_v e4m3 [c][n]; z==8: q(x log2e)+k -> bf16 [n][16].
// ---------------------------------------------------------------------------
__global__ __launch_bounds__(256) void proj_kernel(
    const float* __restrict__ x,
    const float* __restrict__ Wq, const float* __restrict__ bq,
    const float* __restrict__ Wk, const float* __restrict__ bk,
    const float* __restrict__ Wv, const float* __restrict__ bv)
{
    __shared__ float w_t[C * 32];   // [c][o]
    const int t = threadIdx.x;
    const int b = blockIdx.y;
    const int z = blockIdx.z;

    if (z < 8) {
        for (int idx = t; idx < C * 32; idx += 256) {
            int c = idx >> 5, o = idx & 31;
            w_t[idx] = Wv[(size_t)(z * 32 + o) * C + c];
        }
    } else {
        for (int idx = t; idx < C * 32; idx += 256) {
            int c = idx >> 5, o = idx & 31;
            w_t[idx] = (o < 16) ? Wq[(size_t)o * C + c] * LOG2E
                                : Wk[(size_t)(o - 16) * C + c];
        }
    }
    __syncthreads();

    const int n0 = blockIdx.x * 512 + 2 * t;     // pixels n0, n0+1
    const float* xb = x + (size_t)b * C * N + n0;

    u64 a0[16], a1[16];
    if (z < 8) {
        #pragma unroll
        for (int j = 0; j < 16; j++) {
            a0[j] = pk2(bv[z * 32 + 2 * j], bv[z * 32 + 2 * j + 1]);
            a1[j] = a0[j];
        }
    } else {
        #pragma unroll
        for (int j = 0; j < 16; j++) {
            a0[j] = (j < 8) ? pk2(bq[2 * j] * LOG2E, bq[2 * j + 1] * LOG2E)
                            : pk2(bk[2 * (j - 8)], bk[2 * (j - 8) + 1]);
            a1[j] = a0[j];
        }
    }

    #pragma unroll 4
    for (int c = 0; c < C; c++) {
        float2 xv = *(const float2*)&xb[(size_t)c * N];
        u64 xx0 = pk2(xv.x, xv.x);
        u64 xx1 = pk2(xv.y, xv.y);
        const u64* wr = (const u64*)&w_t[c * 32];
        #pragma unroll
        for (int j = 0; j < 16; j++) {
            u64 w = wr[j];
            a0[j] = fma2(xx0, w, a0[j]);
            a1[j] = fma2(xx1, w, a1[j]);
        }
    }

    if (z < 8) {
        #pragma unroll
        for (int j = 0; j < 16; j++) {
            float2 f0 = up2(a0[j]);   // (ch 2j, 2j+1) @ pixel n0
            float2 f1 = up2(a1[j]);   // (ch 2j, 2j+1) @ pixel n0+1
            size_t r0 = ((size_t)b * C + z * 32 + 2 * j) * N + n0;
            *(u16*)(g_v + r0)     = e4m3f2(f0.x, f1.x);
            *(u16*)(g_v + r0 + N) = e4m3f2(f0.y, f1.y);
        }
    } else {
        u32 w0[8], w1[8], k0[8], k1[8];
        #pragma unroll
        for (int j = 0; j < 8; j++) {
            float2 q0 = up2(a0[j]),      q1 = up2(a1[j]);
            float2 kk0 = up2(a0[j + 8]), kk1 = up2(a1[j + 8]);
            w0[j] = bf2(q0.x, q0.y);   w1[j] = bf2(q1.x, q1.y);
            k0[j] = bf2(kk0.x, kk0.y); k1[j] = bf2(kk1.x, kk1.y);
        }
        uint4* qd = (uint4*)&g_q[((size_t)b * N + n0) * CQK];
        qd[0] = make_uint4(w0[0], w0[1], w0[2], w0[3]);
        qd[1] = make_uint4(w0[4], w0[5], w0[6], w0[7]);
        qd[2] = make_uint4(w1[0], w1[1], w1[2], w1[3]);
        qd[3] = make_uint4(w1[4], w1[5], w1[6], w1[7]);
        uint4* kd = (uint4*)&g_k[((size_t)b * N + n0) * CQK];
        kd[0] = make_uint4(k0[0], k0[1], k0[2], k0[3]);
        kd[1] = make_uint4(k0[4], k0[5], k0[6], k0[7]);
        kd[2] = make_uint4(k1[0], k1[1], k1[2], k1[3]);
        kd[3] = make_uint4(k1[4], k1[5], k1[6], k1[7]);
    }
}

// ---------------------------------------------------------------------------
// Flash attention: bf16 S^T (HMMA) -> f16 exp -> e4m3 P^T -> fp8 PV (QMMA).
// Block (m-tile 128, b), 512 threads (16 warps). 1 barrier/tile.
// ---------------------------------------------------------------------------
// smem byte offsets
#define QKS 48                       // q/k row stride (16 bf16 = 32B + 16 pad)
#define PS  80                       // P^T row stride (64 fp8 + 16 pad), 16B-aligned
#define VS  80                       // V row stride  (64 fp8 + 16 pad)
#define SM_L   0                     // 128 f32
#define SM_K   512                   // [128][QKS]
#define SM_Q   (SM_K + 128*QKS)      // 3 x [64][QKS]
#define SM_P   (SM_Q + 3*64*QKS)     // 2 x [128][PS]
#define SM_V   (SM_P + 2*128*PS)     // 3 x [256][VS]
#define SM_TOTAL (SM_V + 3*256*VS)   // 97792 B

__global__ __launch_bounds__(512, 1) void attn_kernel(
    const float* __restrict__ x,
    const float* __restrict__ gamma,
    float* __restrict__ out)
{
    extern __shared__ char smc[];
    float* L_s = (float*)(smc + SM_L);

    const int t    = threadIdx.x;
    const int bb   = blockIdx.y;
    const int m0   = blockIdx.x * MT;
    const int lane = t & 31;
    const int w    = t >> 5;

    // S^T roles: warp = (m16-tile, n32-half)
    const int mt = w & 7;
    const int nh = w >> 3;
    // PV roles: warp = (c32-tile, m64-half)
    const int ct0 = (w & 7) * 32;
    const int mw  = (w >> 3) * 64;

    const int lj = lane >> 3;        // ldmatrix matrix id
    const int li = lane & 7;         // row within matrix
    const int r  = lane >> 2;        // frag row
    const int cq = lane & 3;         // frag col group

    if (t < 128) L_s[t] = 0.f;
    {
        int m = t >> 2, half = (t >> 1) & 1;     // 512 thr cover 128 rows x 2 halves (x2 dup ok)
        if ((t & 1) == 0)
            *(uint4*)(smc + SM_K + m * QKS + half * 16) =
                *(const uint4*)(g_k + ((size_t)bb * N + m0 + m) * CQK + half * 8);
    }

    auto load_qv = [&](int tile) {
        const int n0 = tile * NT;
        const int buf = tile % 3;
        if (t < 128) {
            int n = t >> 1, half = t & 1;
            *(uint4*)(smc + SM_Q + buf * (64 * QKS) + n * QKS + half * 16) =
                *(const uint4*)(g_q + ((size_t)bb * N + n0 + n) * CQK + half * 8);
        }
        char* vd = smc + SM_V + buf * (256 * VS);
        #pragma unroll
        for (int i2 = 0; i2 < 2; i2++) {
            int idx = t + i2 * 512;
            int c = idx >> 2, q = idx & 3;
            *(uint4*)(vd + c * VS + q * 16) =
                *(const uint4*)(g_v + ((size_t)bb * C + c) * N + n0 + q * 16);
        }
    };

    load_qv(0);
    load_qv(1);
    __syncthreads();

    // hoisted K A-frag (constant per block): rows mt*16 + (lj&1)*8 + li
    u32 aK[4];
    ldsm4(aK, smc + SM_K + (mt * 16 + (lj & 1) * 8 + li) * QKS + (lj >> 1) * 16);

    float Lacc0 = 0.f, Lacc8 = 0.f;

    auto s_compute = [&](int tile) {
        const char* qb = smc + SM_Q + (tile % 3) * (64 * QKS);
        u32 bq2[2][4];
        #pragma unroll
        for (int g = 0; g < 2; g++)
            ldsm4(bq2[g], qb + (nh * 32 + g * 16 + (lj >> 1) * 8 + li) * QKS + (lj & 1) * 16);

        float d[4][4];
        #pragma unroll
        for (int j = 0; j < 4; j++)
            #pragma unroll
            for (int e = 0; e < 4; e++) d[j][e] = -SBIAS;
        mma_bf16(d[0], aK, bq2[0]);
        mma_bf16(d[1], aK, bq2[0] + 2);
        mma_bf16(d[2], aK, bq2[1]);
        mma_bf16(d[3], aK, bq2[1] + 2);

        char* pb = smc + SM_P + (tile & 1) * (128 * PS);
        u32 Lt0 = 0, Lt8 = 0;
        #pragma unroll
        for (int nt = 0; nt < 4; nt++) {
            u32 e0 = ex2h2(hpack(d[nt][0], d[nt][1]));   // m = mt*16+r,   n = base, base+1
            u32 e1 = ex2h2(hpack(d[nt][2], d[nt][3]));   // m = mt*16+r+8
            Lt0 = hadd2(Lt0, e0);
            Lt8 = hadd2(Lt8, e1);
            int nb = nh * 32 + nt * 8 + 2 * cq;
            *(u16*)(pb + (mt * 16 + r)     * PS + nb) = e4m3h2(e0);
            *(u16*)(pb + (mt * 16 + r + 8) * PS + nb) = e4m3h2(e1);
        }
        Lacc0 += h2sum(Lt0);
        Lacc8 += h2sum(Lt8);
    };

    float d_acc[2][8][4];
    #pragma unroll
    for (int ct = 0; ct < 2; ct++)
        #pragma unroll
        for (int mp = 0; mp < 8; mp++)
            #pragma unroll
            for (int e = 0; e < 4; e++) d_acc[ct][mp][e] = 0.f;

    s_compute(0);
    __syncthreads();

    for (int tile = 0; tile < NTILES; ++tile) {
        if (tile + 2 < NTILES) load_qv(tile + 2);
        if (tile + 1 < NTILES) s_compute(tile + 1);

        // ---- PV: O += V(tile) @ P^T(tile), fp8 ----
        {
            const char* vc = smc + SM_V + (tile % 3) * (256 * VS);
            const char* pc = smc + SM_P + (tile & 1) * (128 * PS);
            #pragma unroll
            for (int ks = 0; ks < 2; ks++) {
                u32 av[2][4];
                #pragma unroll
                for (int ct = 0; ct < 2; ct++)
                    ldsm4(av[ct], vc + (ct0 + ct * 16 + (lj & 1) * 8 + li) * VS
                                     + ks * 32 + (lj >> 1) * 16);
                #pragma unroll
                for (int mp = 0; mp < 4; mp++) {
                    u32 bf[4];
                    ldsm4(bf, pc + (mw + mp * 16 + (lj >> 1) * 8 + li) * PS
                                 + ks * 32 + (lj & 1) * 16);
                    mma_e4m3(d_acc[0][2 * mp    ], av[0], bf);
                    mma_e4m3(d_acc[0][2 * mp + 1], av[0], bf + 2);
                    mma_e4m3(d_acc[1][2 * mp    ], av[1], bf);
                    mma_e4m3(d_acc[1][2 * mp + 1], av[1], bf + 2);
                }
            }
        }
        __syncthreads();
    }

    // ---- L reduction (once) ----
    Lacc0 += __shfl_xor_sync(0xffffffffu, Lacc0, 1);
    Lacc0 += __shfl_xor_sync(0xffffffffu, Lacc0, 2);
    Lacc8 += __shfl_xor_sync(0xffffffffu, Lacc8, 1);
    Lacc8 += __shfl_xor_sync(0xffffffffu, Lacc8, 2);
    if (cq == 0) {
        atomicAdd(&L_s[mt * 16 + r],     Lacc0);
        atomicAdd(&L_s[mt * 16 + r + 8], Lacc8);
    }
    __syncthreads();
    if (t < 128) L_s[t] = 1.0f / fmaxf(L_s[t], 1e-30f);
    __syncthreads();

    // ---- epilogue: out = x + gamma * O / L ----
    const float g = gamma[0];
    #pragma unroll
    for (int ct = 0; ct < 2; ct++) {
        #pragma unroll
        for (int half = 0; half < 2; half++) {
            int c = ct0 + ct * 16 + r + half * 8;
            #pragma unroll
            for (int mp = 0; mp < 8; mp++) {
                int mloc = mw + mp * 8 + cq * 2;
                float iL0 = L_s[mloc], iL1 = L_s[mloc + 1];
                size_t idx = ((size_t)bb * C + c) * N + m0 + mloc;
                float2 xv = *(const float2*)&x[idx];
                float2 ov;
                ov.x = xv.x + g * d_acc[ct][mp][half * 2    ] * iL0;
                ov.y = xv.y + g * d_acc[ct][mp][half * 2 + 1] * iL1;
                *(float2*)&out[idx] = ov;
            }
        }
    }
}

// ---------------------------------------------------------------------------
extern "C" void kernel_launch(void* const* d_in, const int* in_sizes, int n_in,
                              void* d_out, int out_size)
{
    const float* x     = (const float*)d_in[0];
    const float* Wq    = (const float*)d_in[1];
    const float* bq    = (const float*)d_in[2];
    const float* Wk    = (const float*)d_in[3];
    const float* bk    = (const float*)d_in[4];
    const float* Wv    = (const float*)d_in[5];
    const float* bv    = (const float*)d_in[6];
    const float* gamma = (const float*)d_in[7];
    float* out = (float*)d_out;

    proj_kernel<<<dim3(N / 512, B, 9), 256>>>(x, Wq, bq, Wk, bk, Wv, bv);

    cudaFuncSetAttribute(attn_kernel,
                         cudaFuncAttributeMaxDynamicSharedMemorySize, SM_TOTAL);
    attn_kernel<<<dim3(N / MT, B), 512, SM_TOTAL>>>(x, gamma, out);
}

// round 10
// speedup vs baseline: 1.1484x; 1.0276x over previous
#include <cuda_runtime.h>
#include <cuda_bf16.h>

#define B    4
#define C    256
#define CQK  16
#define MT   64
#define NT   64
#define N    4096
#define NTILES (N / NT)
#define LOG2E 1.4426950408889634f
#define SBIAS 20.0f     // P = 2^(s*log2e - SBIAS); cancels in o/L

typedef unsigned long long u64;
typedef unsigned int u32;
typedef unsigned short u16;
typedef unsigned char u8;

// Scratch: q,k bf16 [B][N][16] (q pre-scaled by log2e); v e4m3 [B][C][N]
__device__ __nv_bfloat16 g_q[(size_t)B * N * CQK];
__device__ __nv_bfloat16 g_k[(size_t)B * N * CQK];
__device__ u8            g_v[(size_t)B * C * N];

// ---- f32x2 helpers (projection) ---------------------------------------------
__device__ __forceinline__ u64 pk2(float lo, float hi) {
    u64 r; asm("mov.b64 %0,{%1,%2};" : "=l"(r) : "f"(lo), "f"(hi)); return r;
}
__device__ __forceinline__ u64 fma2(u64 a, u64 b, u64 c) {
    u64 d; asm("fma.rn.f32x2 %0,%1,%2,%3;" : "=l"(d) : "l"(a), "l"(b), "l"(c)); return d;
}
__device__ __forceinline__ float2 up2(u64 a) {
    float2 f; asm("mov.b64 {%0,%1},%2;" : "=f"(f.x), "=f"(f.y) : "l"(a)); return f;
}

// ---- bf16 / f16 / fp8 helpers --------------------------------------------------
__device__ __forceinline__ u32 bf2(float lo, float hi) {
    u32 r; asm("cvt.rn.bf16x2.f32 %0,%1,%2;" : "=r"(r) : "f"(hi), "f"(lo)); return r;
}
__device__ __forceinline__ u32 hpack(float lo, float hi) {
    u32 r; asm("cvt.rn.f16x2.f32 %0,%1,%2;" : "=r"(r) : "f"(hi), "f"(lo)); return r;
}
__device__ __forceinline__ u32 ex2h2(u32 s) {
    u32 d; asm("ex2.approx.f16x2 %0,%1;" : "=r"(d) : "r"(s)); return d;
}
__device__ __forceinline__ u32 hadd2(u32 a, u32 b) {
    u32 d; asm("add.rn.f16x2 %0,%1,%2;" : "=r"(d) : "r"(a), "r"(b)); return d;
}
__device__ __forceinline__ u16 e4m3h2(u32 h) {
    u16 d; asm("cvt.rn.satfinite.e4m3x2.f16x2 %0,%1;" : "=h"(d) : "r"(h)); return d;
}
__device__ __forceinline__ u16 e4m3f2(float lo, float hi) {
    u16 d; asm("cvt.rn.satfinite.e4m3x2.f32 %0,%1,%2;" : "=h"(d) : "f"(hi), "f"(lo)); return d;
}
__device__ __forceinline__ float h2sum(u32 h) {
    float a, b;
    asm("{.reg .f16 x,y; mov.b32 {x,y},%2; cvt.f32.f16 %0,x; cvt.f32.f16 %1,y;}"
        : "=f"(a), "=f"(b) : "r"(h));
    return a + b;
}

// ---- tensor-core helpers --------------------------------------------------------
__device__ __forceinline__ void ldsm4(u32* r, const void* p) {
    u32 a = (u32)__cvta_generic_to_shared(p);
    asm volatile("ldmatrix.sync.aligned.m8n8.x4.shared.b16 {%0,%1,%2,%3},[%4];"
                 : "=r"(r[0]), "=r"(r[1]), "=r"(r[2]), "=r"(r[3]) : "r"(a));
}
__device__ __forceinline__ void mma_bf16(float* d, const u32* a, const u32* b) {
    asm volatile("mma.sync.aligned.m16n8k16.row.col.f32.bf16.bf16.f32 "
                 "{%0,%1,%2,%3},{%4,%5,%6,%7},{%8,%9},{%0,%1,%2,%3};"
                 : "+f"(d[0]), "+f"(d[1]), "+f"(d[2]), "+f"(d[3])
                 : "r"(a[0]), "r"(a[1]), "r"(a[2]), "r"(a[3]), "r"(b[0]), "r"(b[1]));
}
__device__ __forceinline__ void mma_e4m3(float* d, const u32* a, const u32* b) {
    asm volatile("mma.sync.aligned.m16n8k32.row.col.f32.e4m3.e4m3.f32 "
                 "{%0,%1,%2,%3},{%4,%5,%6,%7},{%8,%9},{%0,%1,%2,%3};"
                 : "+f"(d[0]), "+f"(d[1]), "+f"(d[2]), "+f"(d[3])
                 : "r"(a[0]), "r"(a[1]), "r"(a[2]), "r"(a[3]), "r"(b[0]), "r"(b[1]));
}

// ---------------------------------------------------------------------------
// Projection (unchanged from R9). grid (N/512, B, 9), 256 thr, 2 pixels/thread.
// ---------------------------------------------------------------------------
__global__ __launch_bounds__(256) void proj_kernel(
    const float* __restrict__ x,
    const float* __restrict__ Wq, const float* __restrict__ bq,
    const float* __restrict__ Wk, const float* __restrict__ bk,
    const float* __restrict__ Wv, const float* __restrict__ bv)
{
    __shared__ float w_t[C * 32];   // [c][o]
    const int t = threadIdx.x;
    const int b = blockIdx.y;
    const int z = blockIdx.z;

    if (z < 8) {
        for (int idx = t; idx < C * 32; idx += 256) {
            int c = idx >> 5, o = idx & 31;
            w_t[idx] = Wv[(size_t)(z * 32 + o) * C + c];
        }
    } else {
        for (int idx = t; idx < C * 32; idx += 256) {
            int c = idx >> 5, o = idx & 31;
            w_t[idx] = (o < 16) ? Wq[(size_t)o * C + c] * LOG2E
                                : Wk[(size_t)(o - 16) * C + c];
        }
    }
    __syncthreads();

    const int n0 = blockIdx.x * 512 + 2 * t;
    const float* xb = x + (size_t)b * C * N + n0;

    u64 a0[16], a1[16];
    if (z < 8) {
        #pragma unroll
        for (int j = 0; j < 16; j++) {
            a0[j] = pk2(bv[z * 32 + 2 * j], bv[z * 32 + 2 * j + 1]);
            a1[j] = a0[j];
        }
    } else {
        #pragma unroll
        for (int j = 0; j < 16; j++) {
            a0[j] = (j < 8) ? pk2(bq[2 * j] * LOG2E, bq[2 * j + 1] * LOG2E)
                            : pk2(bk[2 * (j - 8)], bk[2 * (j - 8) + 1]);
            a1[j] = a0[j];
        }
    }

    #pragma unroll 4
    for (int c = 0; c < C; c++) {
        float2 xv = *(const float2*)&xb[(size_t)c * N];
        u64 xx0 = pk2(xv.x, xv.x);
        u64 xx1 = pk2(xv.y, xv.y);
        const u64* wr = (const u64*)&w_t[c * 32];
        #pragma unroll
        for (int j = 0; j < 16; j++) {
            u64 w = wr[j];
            a0[j] = fma2(xx0, w, a0[j]);
            a1[j] = fma2(xx1, w, a1[j]);
        }
    }

    if (z < 8) {
        #pragma unroll
        for (int j = 0; j < 16; j++) {
            float2 f0 = up2(a0[j]);
            float2 f1 = up2(a1[j]);
            size_t r0 = ((size_t)b * C + z * 32 + 2 * j) * N + n0;
            *(u16*)(g_v + r0)     = e4m3f2(f0.x, f1.x);
            *(u16*)(g_v + r0 + N) = e4m3f2(f0.y, f1.y);
        }
    } else {
        u32 w0[8], w1[8], k0[8], k1[8];
        #pragma unroll
        for (int j = 0; j < 8; j++) {
            float2 q0 = up2(a0[j]),      q1 = up2(a1[j]);
            float2 kk0 = up2(a0[j + 8]), kk1 = up2(a1[j + 8]);
            w0[j] = bf2(q0.x, q0.y);   w1[j] = bf2(q1.x, q1.y);
            k0[j] = bf2(kk0.x, kk0.y); k1[j] = bf2(kk1.x, kk1.y);
        }
        uint4* qd = (uint4*)&g_q[((size_t)b * N + n0) * CQK];
        qd[0] = make_uint4(w0[0], w0[1], w0[2], w0[3]);
        qd[1] = make_uint4(w0[4], w0[5], w0[6], w0[7]);
        qd[2] = make_uint4(w1[0], w1[1], w1[2], w1[3]);
        qd[3] = make_uint4(w1[4], w1[5], w1[6], w1[7]);
        uint4* kd = (uint4*)&g_k[((size_t)b * N + n0) * CQK];
        kd[0] = make_uint4(k0[0], k0[1], k0[2], k0[3]);
        kd[1] = make_uint4(k0[4], k0[5], k0[6], k0[7]);
        kd[2] = make_uint4(k1[0], k1[1], k1[2], k1[3]);
        kd[3] = make_uint4(k1[4], k1[5], k1[6], k1[7]);
    }
}

// ---------------------------------------------------------------------------
// Flash attention, 2 CTAs/SM: MT=64, 256 threads (8 warps), fp8 PV.
// ---------------------------------------------------------------------------
#define QKS 48                       // q/k row stride (32B data + 16 pad)
#define PS  80                       // P^T row stride (64 fp8 + 16 pad)
#define VS  80                       // V row stride  (64 fp8 + 16 pad)
#define SM_L   0                     // 64 f32
#define SM_K   512                   // [64][QKS]
#define SM_Q   (SM_K + 64*QKS)       // 3 x [64][QKS]
#define SM_P   (SM_Q + 3*64*QKS)     // 2 x [64][PS]
#define SM_V   (SM_P + 2*64*PS)      // 3 x [256][VS]
#define SM_TOTAL (SM_V + 3*256*VS)   // 84,480 B -> 2 blocks/SM

__global__ __launch_bounds__(256, 2) void attn_kernel(
    const float* __restrict__ x,
    const float* __restrict__ gamma,
    float* __restrict__ out)
{
    extern __shared__ char smc[];
    float* L_s = (float*)(smc + SM_L);

    const int t    = threadIdx.x;
    const int bb   = blockIdx.y;
    const int m0   = blockIdx.x * MT;
    const int lane = t & 31;
    const int w    = t >> 5;

    // S roles: warp = (m16-tile 0..3, n32-half 0..1)
    const int mt = w & 3;
    const int nh = w >> 2;
    // PV roles: warp = c32-tile 0..7, full m-range 64
    const int ct0 = w * 32;

    const int lj = lane >> 3;        // ldmatrix matrix id
    const int li = lane & 7;         // row within matrix
    const int r  = lane >> 2;        // frag row
    const int cq = lane & 3;         // frag col group

    if (t < MT) L_s[t] = 0.f;
    if (t < 128) {
        int m = t >> 1, half = t & 1;
        *(uint4*)(smc + SM_K + m * QKS + half * 16) =
            *(const uint4*)(g_k + ((size_t)bb * N + m0 + m) * CQK + half * 8);
    }

    auto load_qv = [&](int tile) {
        const int n0 = tile * NT;
        const int buf = tile % 3;
        if (t < 128) {
            int n = t >> 1, half = t & 1;
            *(uint4*)(smc + SM_Q + buf * (64 * QKS) + n * QKS + half * 16) =
                *(const uint4*)(g_q + ((size_t)bb * N + n0 + n) * CQK + half * 8);
        }
        char* vd = smc + SM_V + buf * (256 * VS);
        #pragma unroll
        for (int i4 = 0; i4 < 4; i4++) {
            int idx = t + i4 * 256;
            int c = idx >> 2, q = idx & 3;
            *(uint4*)(vd + c * VS + q * 16) =
                *(const uint4*)(g_v + ((size_t)bb * C + c) * N + n0 + q * 16);
        }
    };

    load_qv(0);
    load_qv(1);
    __syncthreads();

    // hoisted K A-frag (constant per block)
    u32 aK[4];
    ldsm4(aK, smc + SM_K + (mt * 16 + (lj & 1) * 8 + li) * QKS + (lj >> 1) * 16);

    float Lacc0 = 0.f, Lacc8 = 0.f;

    auto s_compute = [&](int tile) {
        const char* qb = smc + SM_Q + (tile % 3) * (64 * QKS);
        u32 bq2[2][4];
        #pragma unroll
        for (int g = 0; g < 2; g++)
            ldsm4(bq2[g], qb + (nh * 32 + g * 16 + (lj >> 1) * 8 + li) * QKS + (lj & 1) * 16);

        float d[4][4];
        #pragma unroll
        for (int j = 0; j < 4; j++)
            #pragma unroll
            for (int e = 0; e < 4; e++) d[j][e] = -SBIAS;
        mma_bf16(d[0], aK, bq2[0]);
        mma_bf16(d[1], aK, bq2[0] + 2);
        mma_bf16(d[2], aK, bq2[1]);
        mma_bf16(d[3], aK, bq2[1] + 2);

        char* pb = smc + SM_P + (tile & 1) * (64 * PS);
        u32 Lt0 = 0, Lt8 = 0;
        #pragma unroll
        for (int nt = 0; nt < 4; nt++) {
            u32 e0 = ex2h2(hpack(d[nt][0], d[nt][1]));   // m = mt*16+r
            u32 e1 = ex2h2(hpack(d[nt][2], d[nt][3]));   // m = mt*16+r+8
            Lt0 = hadd2(Lt0, e0);
            Lt8 = hadd2(Lt8, e1);
            int nb = nh * 32 + nt * 8 + 2 * cq;
            *(u16*)(pb + (mt * 16 + r)     * PS + nb) = e4m3h2(e0);
            *(u16*)(pb + (mt * 16 + r + 8) * PS + nb) = e4m3h2(e1);
        }
        Lacc0 += h2sum(Lt0);
        Lacc8 += h2sum(Lt8);
    };

    float d_acc[2][8][4];
    #pragma unroll
    for (int ct = 0; ct < 2; ct++)
        #pragma unroll
        for (int mp = 0; mp < 8; mp++)
            #pragma unroll
            for (int e = 0; e < 4; e++) d_acc[ct][mp][e] = 0.f;

    s_compute(0);
    __syncthreads();

    for (int tile = 0; tile < NTILES; ++tile) {
        if (tile + 2 < NTILES) load_qv(tile + 2);
        if (tile + 1 < NTILES) s_compute(tile + 1);

        // ---- PV: O += V(tile) @ P^T(tile), fp8, full m=64 per warp ----
        {
            const char* vc = smc + SM_V + (tile % 3) * (256 * VS);
            const char* pc = smc + SM_P + (tile & 1) * (64 * PS);
            #pragma unroll
            for (int ks = 0; ks < 2; ks++) {
                u32 av[2][4];
                #pragma unroll
                for (int ct = 0; ct < 2; ct++)
                    ldsm4(av[ct], vc + (ct0 + ct * 16 + (lj & 1) * 8 + li) * VS
                                     + ks * 32 + (lj >> 1) * 16);
                #pragma unroll
                for (int mp = 0; mp < 4; mp++) {
                    u32 bf[4];
                    ldsm4(bf, pc + (mp * 16 + (lj >> 1) * 8 + li) * PS
                                 + ks * 32 + (lj & 1) * 16);
                    mma_e4m3(d_acc[0][2 * mp    ], av[0], bf);
                    mma_e4m3(d_acc[0][2 * mp + 1], av[0], bf + 2);
                    mma_e4m3(d_acc[1][2 * mp    ], av[1], bf);
                    mma_e4m3(d_acc[1][2 * mp + 1], av[1], bf + 2);
                }
            }
        }
        __syncthreads();
    }

    // ---- L reduction (once) ----
    Lacc0 += __shfl_xor_sync(0xffffffffu, Lacc0, 1);
    Lacc0 += __shfl_xor_sync(0xffffffffu, Lacc0, 2);
    Lacc8 += __shfl_xor_sync(0xffffffffu, Lacc8, 1);
    Lacc8 += __shfl_xor_sync(0xffffffffu, Lacc8, 2);
    if (cq == 0) {
        atomicAdd(&L_s[mt * 16 + r],     Lacc0);
        atomicAdd(&L_s[mt * 16 + r + 8], Lacc8);
    }
    __syncthreads();
    if (t < MT) L_s[t] = 1.0f / fmaxf(L_s[t], 1e-30f);
    __syncthreads();

    // ---- epilogue: out = x + gamma * O / L ----
    const float g = gamma[0];
    #pragma unroll
    for (int ct = 0; ct < 2; ct++) {
        #pragma unroll
        for (int half = 0; half < 2; half++) {
            int c = ct0 + ct * 16 + r + half * 8;
            #pragma unroll
            for (int mp = 0; mp < 8; mp++) {
                int mloc = mp * 8 + cq * 2;
                float iL0 = L_s[mloc], iL1 = L_s[mloc + 1];
                size_t idx = ((size_t)bb * C + c) * N + m0 + mloc;
                float2 xv = *(const float2*)&x[idx];
                float2 ov;
                ov.x = xv.x + g * d_acc[ct][mp][half * 2    ] * iL0;
                ov.y = xv.y + g * d_acc[ct][mp][half * 2 + 1] * iL1;
                *(float2*)&out[idx] = ov;
            }
        }
    }
}

// ---------------------------------------------------------------------------
extern "C" void kernel_launch(void* const* d_in, const int* in_sizes, int n_in,
                              void* d_out, int out_size)
{
    const float* x     = (const float*)d_in[0];
    const float* Wq    = (const float*)d_in[1];
    const float* bq    = (const float*)d_in[2];
    const float* Wk    = (const float*)d_in[3];
    const float* bk    = (const float*)d_in[4];
    const float* Wv    = (const float*)d_in[5];
    const float* bv    = (const float*)d_in[6];
    const float* gamma = (const float*)d_in[7];
    float* out = (float*)d_out;

    proj_kernel<<<dim3(N / 512, B, 9), 256>>>(x, Wq, bq, Wk, bk, Wv, bv);

    cudaFuncSetAttribute(attn_kernel,
                         cudaFuncAttributeMaxDynamicSharedMemorySize, SM_TOTAL);
    attn_kernel<<<dim3(N / MT, B), 256, SM_TOTAL>>>(x, gamma, out);
}